// round 16
// baseline (speedup 1.0000x reference)
#include <cuda_runtime.h>
#include <cuda_fp16.h>
#include <cstdint>

#define SL 4096
#define SD 512

// layout (float units): qh(1M) | kh(1M) | vth(1M) | omh(1M) | xph(1M) | Wh(512K) | rel2(64K)
#define OFF_QH   0u
#define OFF_KH   (1u * 1024 * 1024)
#define OFF_VTH  (2u * 1024 * 1024)
#define OFF_OMH  (3u * 1024 * 1024)
#define OFF_XPH  (4u * 1024 * 1024)
#define OFF_WH   (5u * 1024 * 1024)
#define OFF_REL2 (OFF_WH + 4u * (SD * SD / 2))
__device__ float g_scratch[6 * 1024 * 1024];

#define LOG2E 1.44269504088896f

__device__ __forceinline__ uint32_t smem_u32(const void* p) {
    return (uint32_t)__cvta_generic_to_shared(p);
}
__device__ __forceinline__ uint32_t h2pack(float lo, float hi) {
    __half2 h = __floats2half2_rn(lo, hi);
    return *reinterpret_cast<uint32_t*>(&h);
}
__device__ __forceinline__ uint32_t ex2h2(uint32_t x) {
    uint32_t r;
    asm("ex2.approx.f16x2 %0, %1;" : "=r"(r) : "r"(x));
    return r;
}

__device__ __forceinline__ void mma_f16(float& d0, float& d1, float& d2, float& d3,
                                        uint32_t a0, uint32_t a1, uint32_t a2, uint32_t a3,
                                        uint32_t b0, uint32_t b1) {
    asm volatile(
        "mma.sync.aligned.m16n8k16.row.col.f32.f16.f16.f32 "
        "{%0,%1,%2,%3}, {%4,%5,%6,%7}, {%8,%9}, {%0,%1,%2,%3};"
        : "+f"(d0), "+f"(d1), "+f"(d2), "+f"(d3)
        : "r"(a0), "r"(a1), "r"(a2), "r"(a3), "r"(b0), "r"(b1));
}

#define LDSM4(r0, r1, r2, r3, addr)                                            \
    asm volatile("ldmatrix.sync.aligned.m8n8.x4.shared.b16 {%0,%1,%2,%3}, [%4];" \
                 : "=r"(r0), "=r"(r1), "=r"(r2), "=r"(r3) : "r"(addr))
#define LDSM4T(r0, r1, r2, r3, addr)                                           \
    asm volatile("ldmatrix.sync.aligned.m8n8.x4.trans.shared.b16 {%0,%1,%2,%3}, [%4];" \
                 : "=r"(r0), "=r"(r1), "=r"(r2), "=r"(r3) : "r"(addr))

#define CP16(dst, src) \
    asm volatile("cp.async.cg.shared.global [%0], [%1], 16;\n" ::"r"(dst), "l"(src))
#define CP4(dst, src) \
    asm volatile("cp.async.ca.shared.global [%0], [%1], 4;\n" ::"r"(dst), "l"(src))
#define CPCOMMIT() asm volatile("cp.async.commit_group;\n")
#define CPWAIT0() asm volatile("cp.async.wait_group 0;\n")
#define CPWAIT1() asm volatile("cp.async.wait_group 1;\n")
#define CPWAIT2() asm volatile("cp.async.wait_group 2;\n")

// ---------------------------------------------------------------------------
// prep: fp16(x+pos), fp16 weights, rel * log2e (float). Vectorized float4.
// ---------------------------------------------------------------------------
__global__ __launch_bounds__(256) void prep_kernel(const float* __restrict__ x,
                                                   const float* __restrict__ pos,
                                                   const float* __restrict__ rel,
                                                   const float* __restrict__ Wq,
                                                   const float* __restrict__ Wk,
                                                   const float* __restrict__ Wv,
                                                   const float* __restrict__ Wo)
{
    uint32_t* xph  = (uint32_t*)(g_scratch + OFF_XPH);   // half2 units
    uint32_t* wh   = (uint32_t*)(g_scratch + OFF_WH);
    float*    rel2 = g_scratch + OFF_REL2;
    const int gsz = gridDim.x * blockDim.x;
    const int gid = blockIdx.x * blockDim.x + threadIdx.x;

    const float4* x4 = (const float4*)x;
    const float4* p4 = (const float4*)pos;
    for (int i = gid; i < SL * SD / 4; i += gsz) {
        float4 xv = x4[i], pv = p4[i];
        xph[2 * i]     = h2pack(xv.x + pv.x, xv.y + pv.y);
        xph[2 * i + 1] = h2pack(xv.z + pv.z, xv.w + pv.w);
    }
    const float4* wq4 = (const float4*)Wq;
    const float4* wk4 = (const float4*)Wk;
    const float4* wv4 = (const float4*)Wv;
    const float4* wo4 = (const float4*)Wo;
    const int wstep = SD * SD / 2;   // half2 units per matrix
    for (int i = gid; i < SD * SD / 4; i += gsz) {
        float4 v;
        v = wq4[i];
        wh[2 * i]     = h2pack(v.x, v.y);
        wh[2 * i + 1] = h2pack(v.z, v.w);
        v = wk4[i];
        wh[wstep + 2 * i]     = h2pack(v.x, v.y);
        wh[wstep + 2 * i + 1] = h2pack(v.z, v.w);
        v = wv4[i];
        wh[2 * wstep + 2 * i]     = h2pack(v.x, v.y);
        wh[2 * wstep + 2 * i + 1] = h2pack(v.z, v.w);
        v = wo4[i];
        wh[3 * wstep + 2 * i]     = h2pack(v.x, v.y);
        wh[3 * wstep + 2 * i + 1] = h2pack(v.z, v.w);
    }
    const float4* r4 = (const float4*)rel;
    float4* r24 = (float4*)rel2;
    for (int i = gid; i < 8 * 2 * SL / 4; i += gsz) {
        float4 v = r4[i];
        v.x *= LOG2E; v.y *= LOG2E; v.z *= LOG2E; v.w *= LOG2E;
        r24[i] = v;
    }
}

// ---------------------------------------------------------------------------
// fp16 GEMM: BM=64 BN=128 BK=32, 8 warps (warp tile 32x32), 4-stage cp.async
// pipeline (prefetch depth 3), 1 barrier per k-step, 3 CTAs/SM.
// mode 0: fp32 out. mode 1: fp16 row-major. mode 2: fp16 transposed (vT).
// ---------------------------------------------------------------------------
#define GA_STG 5120                // 64 rows x 80 B
#define GB_STG 8704                // 32 rows x 272 B
#define G_STG  (GA_STG + GB_STG)
#define GEMM_SMEM (4 * G_STG)

__device__ __forceinline__ void gemm_body(const __half* __restrict__ A,
                                          const __half* __restrict__ Bm,
                                          const float* __restrict__ bias,
                                          float* __restrict__ Cf,
                                          __half* __restrict__ Ch,
                                          float scale, int mode)
{
    extern __shared__ uint8_t gsmb[];
    const uint32_t sbb = smem_u32(gsmb);
    const int tid  = threadIdx.x;
    const int warp = tid >> 5, lane = tid & 31;
    const int g    = lane >> 2, tg = lane & 3;
    const int wr   = warp >> 2, wc = warp & 3;
    const int m0   = blockIdx.x * 64, n0 = blockIdx.y * 128;

    auto loadAB = [&](int t, int s) {
        if (t < 16) {
            const int kt = t * 32;
            uint32_t ab = sbb + s * G_STG;
            uint32_t bb = ab + GA_STG;
            {
                int r = tid >> 2, c = tid & 3;
                CP16(ab + r * 80 + c * 16, A + (size_t)(m0 + r) * 512 + kt + c * 8);
            }
#pragma unroll
            for (int i = 0; i < 2; i++) {
                int idx = tid + i * 256;
                int r = idx >> 4, c = idx & 15;
                CP16(bb + r * 272 + c * 16, Bm + (size_t)(kt + r) * 512 + n0 + c * 8);
            }
        }
        CPCOMMIT();
    };

    float acc[2][4][4];
#pragma unroll
    for (int mt = 0; mt < 2; mt++)
#pragma unroll
        for (int nt = 0; nt < 4; nt++)
#pragma unroll
            for (int r = 0; r < 4; r++) acc[mt][nt][r] = 0.f;

    loadAB(0, 0);
    loadAB(1, 1);
    loadAB(2, 2);

    const uint32_t lrow = (lane & 7) + 8 * ((lane >> 3) & 1);
    const uint32_t lseg = (lane >> 4) * 16;

    int s = 0;
    for (int t = 0; t < 16; t++) {
        CPWAIT2();
        __syncthreads();
        int s3 = s + 3; if (s3 >= 4) s3 -= 4;
        loadAB(t + 3, s3);
        const uint32_t ab = sbb + s * G_STG;
        const uint32_t bb = ab + GA_STG;
#pragma unroll
        for (int ks = 0; ks < 2; ks++) {
            uint32_t af[2][4];
#pragma unroll
            for (int mt = 0; mt < 2; mt++)
                LDSM4(af[mt][0], af[mt][1], af[mt][2], af[mt][3],
                      ab + (wr * 32 + mt * 16 + lrow) * 80 + lseg + ks * 32);
#pragma unroll
            for (int pair = 0; pair < 2; pair++) {
                uint32_t b0, b1, b2, b3;
                LDSM4T(b0, b1, b2, b3,
                       bb + (ks * 16 + lrow) * 272 + wc * 64 + pair * 32 + lseg);
#pragma unroll
                for (int mt = 0; mt < 2; mt++) {
                    mma_f16(acc[mt][2 * pair][0], acc[mt][2 * pair][1],
                            acc[mt][2 * pair][2], acc[mt][2 * pair][3],
                            af[mt][0], af[mt][1], af[mt][2], af[mt][3], b0, b1);
                    mma_f16(acc[mt][2 * pair + 1][0], acc[mt][2 * pair + 1][1],
                            acc[mt][2 * pair + 1][2], acc[mt][2 * pair + 1][3],
                            af[mt][0], af[mt][1], af[mt][2], af[mt][3], b2, b3);
                }
            }
        }
        if (++s >= 4) s -= 4;
    }

#pragma unroll
    for (int mt = 0; mt < 2; mt++) {
        int row = m0 + wr * 32 + mt * 16 + g;
#pragma unroll
        for (int nt = 0; nt < 4; nt++) {
            int col = n0 + wc * 32 + nt * 8 + 2 * tg;
            float b0 = bias[col], b1 = bias[col + 1];
            float v00 = (acc[mt][nt][0] + b0) * scale;
            float v01 = (acc[mt][nt][1] + b1) * scale;
            float v10 = (acc[mt][nt][2] + b0) * scale;
            float v11 = (acc[mt][nt][3] + b1) * scale;
            if (mode == 0) {
                Cf[(size_t)row * 512 + col]           = v00;
                Cf[(size_t)row * 512 + col + 1]       = v01;
                Cf[(size_t)(row + 8) * 512 + col]     = v10;
                Cf[(size_t)(row + 8) * 512 + col + 1] = v11;
            } else if (mode == 1) {
                *reinterpret_cast<__half2*>(&Ch[(size_t)row * 512 + col]) =
                    __floats2half2_rn(v00, v01);
                *reinterpret_cast<__half2*>(&Ch[(size_t)(row + 8) * 512 + col]) =
                    __floats2half2_rn(v10, v11);
            } else {
                Ch[(size_t)col * SL + row]           = __float2half_rn(v00);
                Ch[(size_t)(col + 1) * SL + row]     = __float2half_rn(v01);
                Ch[(size_t)col * SL + row + 8]       = __float2half_rn(v10);
                Ch[(size_t)(col + 1) * SL + row + 8] = __float2half_rn(v11);
            }
        }
    }
}

__global__ __launch_bounds__(256, 3) void qkv_kernel(const float* __restrict__ bq,
                                                     const float* __restrict__ bk,
                                                     const float* __restrict__ bv)
{
    const __half* xph = (const __half*)(g_scratch + OFF_XPH);
    const __half* wh  = (const __half*)(g_scratch + OFF_WH);
    int z = blockIdx.z;
    const __half* Bm = wh + (size_t)z * SD * SD;
    const float* bi  = (z == 0) ? bq : (z == 1) ? bk : bv;
    __half* Ch       = (__half*)(g_scratch + (size_t)z * 1024 * 1024);
    float scale = (z == 0) ? 0.125f * LOG2E : 1.0f;   // q carries 1/8 * log2e
    gemm_body(xph, Bm, bi, nullptr, Ch, scale, (z == 2) ? 2 : 1);
}

__global__ __launch_bounds__(256, 3) void proj_kernel(const float* __restrict__ bo,
                                                      float* __restrict__ out)
{
    const __half* omh = (const __half*)(g_scratch + OFF_OMH);
    const __half* woh = (const __half*)(g_scratch + OFF_WH) + 3 * SD * SD;
    gemm_body(omh, woh, bo, out, nullptr, 1.0f, 0);
}

// ---------------------------------------------------------------------------
// fp16 flash attention (unchanged from r15 winner): BM=128, BN=64, 8 warps,
// m16n8k16, 3-stage, 1 barrier, ex2.f16x2 softmax, ones-MMA row sums.
// ---------------------------------------------------------------------------
#define QROW 144
#define SMQ_BYTES (128 * QROW)
#define VOFF  9216
#define RBOFF 18432
#define STB   19264
#define ATTN_SMEM (SMQ_BYTES + 3 * STB)
#define ONES_H2 0x3C003C00u

__global__ __launch_bounds__(256, 2) void attn_kernel()
{
    extern __shared__ uint8_t smb[];
    const uint32_t sb = smem_u32(smb);

    const __half* qh   = (const __half*)(g_scratch + OFF_QH);
    const __half* kh   = (const __half*)(g_scratch + OFF_KH);
    const __half* vth  = (const __half*)(g_scratch + OFF_VTH);
    __half*       omh  = (__half*)(g_scratch + OFF_OMH);
    const float*  rel2 = g_scratch + OFF_REL2;

    const int tid  = threadIdx.x;
    const int warp = tid >> 5, lane = tid & 31;
    const int g    = lane >> 2, tg = lane & 3;
    const int q0   = blockIdx.x * 128;
    const int h    = blockIdx.y;
    const int rbase = warp * 16;

    // Q tile -> smem -> ldmatrix fragments
#pragma unroll
    for (int i = 0; i < 4; i++) {
        int id = tid + i * 256;
        int r = id >> 3, c = id & 7;
        CP16(sb + r * QROW + c * 16, qh + (size_t)(q0 + r) * 512 + h * 64 + c * 8);
    }
    CPCOMMIT();
    CPWAIT0();
    __syncthreads();

    uint32_t qf[4][4];
    {
        uint32_t qa = sb + (rbase + (lane & 7) + 8 * ((lane >> 3) & 1)) * QROW +
                      (lane >> 4) * 16;
#pragma unroll
        for (int kb = 0; kb < 4; kb++)
            LDSM4(qf[kb][0], qf[kb][1], qf[kb][2], qf[kb][3], qa + kb * 32);
    }

    auto issue = [&](int t, int s) {
        if (t < 64) {
            const int krow0 = t * 64;
            uint32_t st = sb + SMQ_BYTES + s * STB;
#pragma unroll
            for (int i = 0; i < 2; i++) {
                int id = tid + i * 256;
                int r = id >> 3, c = id & 7;
                CP16(st + r * QROW + c * 16,
                     kh + (size_t)(krow0 + r) * 512 + h * 64 + c * 8);
                CP16(st + VOFF + r * QROW + c * 16,
                     vth + (size_t)(h * 64 + r) * SL + krow0 + c * 8);
            }
            if (tid < 192) {
                int base = krow0 - q0 + (SL - 1) - 127;
                CP4(st + RBOFF + tid * 4, rel2 + (size_t)h * 2 * SL + base + tid);
            }
        }
        CPCOMMIT();
    };
    issue(0, 0);
    issue(1, 1);

    float O[8][4];
#pragma unroll
    for (int nb = 0; nb < 8; nb++)
#pragma unroll
        for (int r = 0; r < 4; r++) O[nb][r] = 0.f;
    float La[4] = {0.f, 0.f, 0.f, 0.f};   // ones-MMA row-sum accumulator

    const int i0 = rbase + g, i1 = i0 + 8;
    const int o0 = 127 - i0, o1 = 127 - i1;
    const uint32_t lrow = (lane & 7) + 8 * (lane >> 4);
    const uint32_t lcol = ((lane >> 3) & 1) * 16;

    int s = 0;
    for (int t = 0; t < 64; t++) {
        CPWAIT1();
        __syncthreads();
        int s2 = s + 2; if (s2 >= 3) s2 -= 3;
        issue(t + 2, s2);

        const uint32_t st = sb + SMQ_BYTES + s * STB;
        const float* rb = (const float*)(smb + SMQ_BYTES + s * STB + RBOFF);

        // S accumulators initialized with bias; mma accumulates Q.K^T on top
        float S[8][4];
#pragma unroll
        for (int nb = 0; nb < 8; nb++) {
            int j = nb * 8 + 2 * tg;
            S[nb][0] = rb[j + o0];
            S[nb][1] = rb[j + 1 + o0];
            S[nb][2] = rb[j + o1];
            S[nb][3] = rb[j + 1 + o1];
        }

        const uint32_t kadd = st + lrow * QROW + lcol;
#pragma unroll
        for (int kb = 0; kb < 4; kb++) {
#pragma unroll
            for (int j = 0; j < 4; j++) {
                uint32_t b0, b1, b2, b3;
                LDSM4(b0, b1, b2, b3, kadd + j * (16 * QROW) + kb * 32);
                mma_f16(S[2 * j][0], S[2 * j][1], S[2 * j][2], S[2 * j][3],
                        qf[kb][0], qf[kb][1], qf[kb][2], qf[kb][3], b0, b1);
                mma_f16(S[2 * j + 1][0], S[2 * j + 1][1], S[2 * j + 1][2], S[2 * j + 1][3],
                        qf[kb][0], qf[kb][1], qf[kb][2], qf[kb][3], b2, b3);
            }
        }

        // P = ex2.f16x2(S) packed straight into A-fragments (C->A identity)
        uint32_t pa[4][4];
#pragma unroll
        for (int kb = 0; kb < 4; kb++) {
            pa[kb][0] = ex2h2(h2pack(S[2 * kb][0], S[2 * kb][1]));
            pa[kb][1] = ex2h2(h2pack(S[2 * kb][2], S[2 * kb][3]));
            pa[kb][2] = ex2h2(h2pack(S[2 * kb + 1][0], S[2 * kb + 1][1]));
            pa[kb][3] = ex2h2(h2pack(S[2 * kb + 1][2], S[2 * kb + 1][3]));
        }

        // Row sums L += P @ ones  (fp32, exact sums of the fp16 P used below)
#pragma unroll
        for (int kb = 0; kb < 4; kb++)
            mma_f16(La[0], La[1], La[2], La[3],
                    pa[kb][0], pa[kb][1], pa[kb][2], pa[kb][3], ONES_H2, ONES_H2);

        // O += P @ V
        const uint32_t vadd = st + VOFF + lrow * QROW + lcol;
#pragma unroll
        for (int kb = 0; kb < 4; kb++) {
#pragma unroll
            for (int jd = 0; jd < 4; jd++) {
                uint32_t b0, b1, b2, b3;
                LDSM4(b0, b1, b2, b3, vadd + jd * (16 * QROW) + kb * 32);
                mma_f16(O[2 * jd][0], O[2 * jd][1], O[2 * jd][2], O[2 * jd][3],
                        pa[kb][0], pa[kb][1], pa[kb][2], pa[kb][3], b0, b1);
                mma_f16(O[2 * jd + 1][0], O[2 * jd + 1][1], O[2 * jd + 1][2], O[2 * jd + 1][3],
                        pa[kb][0], pa[kb][1], pa[kb][2], pa[kb][3], b2, b3);
            }
        }

        if (++s >= 3) s -= 3;
    }

    // La[0]/La[2] hold the complete row sums for rows i0 / i1 (all lanes agree)
    const float il0 = 1.f / La[0], il1 = 1.f / La[2];
    const int row0 = q0 + i0;
#pragma unroll
    for (int nb = 0; nb < 8; nb++) {
        int col = h * 64 + nb * 8 + 2 * tg;
        *reinterpret_cast<__half2*>(&omh[(size_t)row0 * 512 + col]) =
            __floats2half2_rn(O[nb][0] * il0, O[nb][1] * il0);
        *reinterpret_cast<__half2*>(&omh[(size_t)(row0 + 8) * 512 + col]) =
            __floats2half2_rn(O[nb][2] * il1, O[nb][3] * il1);
    }
}

// ---------------------------------------------------------------------------
extern "C" void kernel_launch(void* const* d_in, const int* in_sizes, int n_in,
                              void* d_out, int out_size)
{
    const float* x   = (const float*)d_in[0];
    const float* pos = (const float*)d_in[1];
    const float* rel = (const float*)d_in[2];
    const float* Wq  = (const float*)d_in[3];
    const float* bq  = (const float*)d_in[4];
    const float* Wk  = (const float*)d_in[5];
    const float* bk  = (const float*)d_in[6];
    const float* Wv  = (const float*)d_in[7];
    const float* bv  = (const float*)d_in[8];
    const float* Wo  = (const float*)d_in[9];
    const float* bo  = (const float*)d_in[10];
    float* out = (float*)d_out;

    cudaFuncSetAttribute(attn_kernel, cudaFuncAttributeMaxDynamicSharedMemorySize,
                         ATTN_SMEM);
    cudaFuncSetAttribute(qkv_kernel, cudaFuncAttributeMaxDynamicSharedMemorySize,
                         GEMM_SMEM);
    cudaFuncSetAttribute(proj_kernel, cudaFuncAttributeMaxDynamicSharedMemorySize,
                         GEMM_SMEM);

    prep_kernel<<<592, 256>>>(x, pos, rel, Wq, Wk, Wv, Wo);
    qkv_kernel<<<dim3(64, 4, 3), 256, GEMM_SMEM>>>(bq, bk, bv);
    attn_kernel<<<dim3(32, 8), 256, ATTN_SMEM>>>();
    proj_kernel<<<dim3(64, 4), 256, GEMM_SMEM>>>(bo, out);
}